// round 14
// baseline (speedup 1.0000x reference)
#include <cuda_runtime.h>
#include <math_constants.h>

// Problem geometry
#define NSRC 16384
#define NTAR 16384

// 2D grid over (x,y)
#define GB   5.0f                 // half-extent; N(0,1) data max |coord| ~4.3
#define GC   64                   // cells per dim
#define HH   0.15625f             // 2*GB/GC
#define INVH 6.4f                 // 1/HH
#define NCELL (GC * GC)           // 4096
#define CAP  128                  // per-cell capacity (center cells ~64; overflow -> fallback)
#define OCAP 1024                 // fallback list capacity

#define SB   2048                 // search blocks (8 targets each, warp-per-target)
#define NTHREADS 256

// Scratch (allocation-free rule: __device__ globals; zero-initialized at load,
// every counter reset by the last search block for graph replay).
__device__ int    g_cnt[NCELL];
__device__ float4 g_cell[NCELL * CAP];      // (x,y,z, -0.5*||s||^2)
__device__ float4 g_out_list[OCAP];
__device__ int    g_nout = 0;
__device__ float  g_partial[SB];
__device__ int    g_ctr = 0;

// ---------------------------------------------------------------------------
// Build: scatter sources into per-cell lists. Order within a cell is
// nondeterministic, but consumers take an order-invariant exact max.
// ---------------------------------------------------------------------------
__global__ __launch_bounds__(NTHREADS) void build_kernel(const float* __restrict__ src) {
    int i = blockIdx.x * NTHREADS + threadIdx.x;
    if (i >= NSRC) return;
    float x = src[3 * i + 0];
    float y = src[3 * i + 1];
    float z = src[3 * i + 2];
    float w = -0.5f * (x * x + y * y + z * z);
    int ix = (int)floorf((x + GB) * INVH);
    int iy = (int)floorf((y + GB) * INVH);
    if (ix >= 0 && ix < GC && iy >= 0 && iy < GC) {
        int c = iy * GC + ix;
        int p = atomicAdd(&g_cnt[c], 1);
        if (p < CAP) {
            g_cell[c * CAP + p] = make_float4(x, y, z, w);
            return;
        }
    }
    // out-of-range or cell overflow: exact fallback list (scanned by everyone)
    int o = atomicAdd(&g_nout, 1);
    if (o < OCAP) g_out_list[o] = make_float4(x, y, z, w);
}

// ---------------------------------------------------------------------------
// Search helpers
// ---------------------------------------------------------------------------
__device__ __forceinline__ float warp_max(float v) {
#pragma unroll
    for (int o = 16; o > 0; o >>= 1)
        v = fmaxf(v, __shfl_xor_sync(0xFFFFFFFFu, v, o));
    return v;
}

// Dense scan of one ROW of up to 3 adjacent cells (cx-1..cx+1) with
// pre-fetched counts. Candidates walked as one flattened index space:
// all loads in the loop are address-independent -> deep MLP.
__device__ __forceinline__ void scan_row3(int y, int cx, int n0, int n1, int n2,
                                          float tx, float ty, float tz,
                                          int lane, float& vmax) {
    int p1 = n0, p2 = n0 + n1, N = p2 + n2;
    // base may correspond to cx-1 = -1; cells with count 0 are never selected.
    const float4* base = g_cell + (long long)(y * GC + cx - 1) * CAP;
    for (int i = lane; i < N; i += 32) {
        int ge1 = (i >= p1) ? 1 : 0;
        int ge2 = (i >= p2) ? 1 : 0;
        int cell = ge1 + ge2;                       // 0,1,2
        int sub  = i - (ge2 ? p2 : (ge1 ? p1 : 0)); // index within cell
        float4 p = __ldg(base + cell * CAP + sub);
        float v = fmaf(p.x, tx, fmaf(p.y, ty, fmaf(p.z, tz, p.w)));
        vmax = fmaxf(vmax, v);
    }
}

// Slow-path single-cell scan (rings r>=2; rare)
__device__ __forceinline__ void scan_cell(int c, float tx, float ty, float tz,
                                          int lane, float& vmax) {
    int n = min(g_cnt[c], CAP);
    const float4* pl = g_cell + c * CAP;
    for (int i = lane; i < n; i += 32) {
        float4 p = __ldg(&pl[i]);
        float v = fmaf(p.x, tx, fmaf(p.y, ty, fmaf(p.z, tz, p.w)));
        vmax = fmaxf(vmax, v);
    }
}

// ---------------------------------------------------------------------------
// Search: one target per WARP. Fast path scans the full 3x3 window with
// prefetched counts + dense flattened row loops (high MLP). Exact margin
// termination; rare unresolved targets continue with classic ring expansion.
// ---------------------------------------------------------------------------
__global__ __launch_bounds__(NTHREADS) void search_kernel(const float* __restrict__ tar,
                                                          float* __restrict__ out) {
    __shared__ float wsum[NTHREADS / 32];
    __shared__ bool  amLast;
    __shared__ float red[NTHREADS];

    const int lane = threadIdx.x & 31;
    const int wid  = threadIdx.x >> 5;
    const int t    = blockIdx.x * (NTHREADS / 32) + wid;   // one target per warp

    const float tx = tar[3 * t + 0];
    const float ty = tar[3 * t + 1];
    const float tz = tar[3 * t + 2];
    const float ht2 = 0.5f * (tx * tx + ty * ty + tz * tz);

    int cx = min(GC - 1, max(0, (int)floorf((tx + GB) * INVH)));
    int cy = min(GC - 1, max(0, (int)floorf((ty + GB) * INVH)));

    float vmax = -CUDART_INF_F;

    // Fallback list (almost always empty)
    int no = min(g_nout, OCAP);
    for (int i = lane; i < no; i += 32) {
        float4 p = __ldg(&g_out_list[i]);
        float v = fmaf(p.x, tx, fmaf(p.y, ty, fmaf(p.z, tz, p.w)));
        vmax = fmaxf(vmax, v);
    }

    // ---- fast path: full 3x3 window, counts prefetched (9 independent LDG) --
    int cnt[3][3];
#pragma unroll
    for (int dy = 0; dy < 3; dy++) {
        int yy = cy - 1 + dy;
#pragma unroll
        for (int dx = 0; dx < 3; dx++) {
            int xx = cx - 1 + dx;
            cnt[dy][dx] = (yy >= 0 && yy < GC && xx >= 0 && xx < GC)
                          ? min(g_cnt[yy * GC + xx], CAP) : 0;
        }
    }
#pragma unroll
    for (int dy = 0; dy < 3; dy++) {
        int yy = cy - 1 + dy;
        if (yy >= 0 && yy < GC)
            scan_row3(yy, cx, cnt[dy][0], cnt[dy][1], cnt[dy][2],
                      tx, ty, tz, lane, vmax);
    }

    int x0 = max(0, cx - 1), x1 = min(GC - 1, cx + 1);
    int y0 = max(0, cy - 1), y1 = min(GC - 1, cy + 1);

    float vred = warp_max(vmax);
    {
        float mL = (x0 > 0)      ? (tx - (-GB + (float)x0 * HH))        : CUDART_INF_F;
        float mR = (x1 < GC - 1) ? ((-GB + (float)(x1 + 1) * HH) - tx)  : CUDART_INF_F;
        float mB = (y0 > 0)      ? (ty - (-GB + (float)y0 * HH))        : CUDART_INF_F;
        float mT = (y1 < GC - 1) ? ((-GB + (float)(y1 + 1) * HH) - ty)  : CUDART_INF_F;
        float margin = fminf(fminf(mL, mR), fminf(mB, mT));
        if (ht2 - vred > 0.5f * margin * margin) {
            // ---- slow path: classic ring expansion from r = 2 (rare) -------
            for (int r = 2; r < GC; r++) {
                x0 = max(0, cx - r); x1 = min(GC - 1, cx + r);
                y0 = max(0, cy - r); y1 = min(GC - 1, cy + r);
                if (cy - r >= 0) {
                    int base = (cy - r) * GC;
                    for (int x = x0; x <= x1; x++)
                        scan_cell(base + x, tx, ty, tz, lane, vmax);
                }
                if (cy + r <= GC - 1) {
                    int base = (cy + r) * GC;
                    for (int x = x0; x <= x1; x++)
                        scan_cell(base + x, tx, ty, tz, lane, vmax);
                }
                int yy0 = max(0, cy - r + 1), yy1 = min(GC - 1, cy + r - 1);
                if (cx - r >= 0)
                    for (int y = yy0; y <= yy1; y++)
                        scan_cell(y * GC + (cx - r), tx, ty, tz, lane, vmax);
                if (cx + r <= GC - 1)
                    for (int y = yy0; y <= yy1; y++)
                        scan_cell(y * GC + (cx + r), tx, ty, tz, lane, vmax);

                vred = warp_max(vmax);
                mL = (x0 > 0)      ? (tx - (-GB + (float)x0 * HH))        : CUDART_INF_F;
                mR = (x1 < GC - 1) ? ((-GB + (float)(x1 + 1) * HH) - tx)  : CUDART_INF_F;
                mB = (y0 > 0)      ? (ty - (-GB + (float)y0 * HH))        : CUDART_INF_F;
                mT = (y1 < GC - 1) ? ((-GB + (float)(y1 + 1) * HH) - ty)  : CUDART_INF_F;
                margin = fminf(fminf(mL, mR), fminf(mB, mT));
                if (ht2 - vred <= 0.5f * margin * margin) break;  // full grid: margin=inf
            }
        }
    }

    // 0.5*min_d2 for this target
    if (lane == 0) wsum[wid] = ht2 - vred;
    __syncthreads();

    // Block reduction over 8 warp results (fixed order)
    if (threadIdx.x == 0) {
        float s = 0.0f;
#pragma unroll
        for (int i = 0; i < NTHREADS / 32; i++) s += wsum[i];
        g_partial[blockIdx.x] = s;
        __threadfence();
        int old = atomicAdd(&g_ctr, 1);
        amLast = (old == SB - 1);
    }
    __syncthreads();
    if (!amLast) return;

    __threadfence();
    // Fixed-order deterministic final sum: thread k sums partials [8k, 8k+8)
    float acc = 0.0f;
#pragma unroll
    for (int i = 0; i < SB / NTHREADS; i++)
        acc += g_partial[threadIdx.x * (SB / NTHREADS) + i];
    red[threadIdx.x] = acc;
    __syncthreads();
#pragma unroll
    for (int stride = NTHREADS / 2; stride > 0; stride >>= 1) {
        if (threadIdx.x < stride) red[threadIdx.x] += red[threadIdx.x + stride];
        __syncthreads();
    }
    if (threadIdx.x == 0) out[0] = red[0];

    // Reset state for next graph replay (all other blocks finished reading)
    for (int i = threadIdx.x; i < NCELL; i += NTHREADS) g_cnt[i] = 0;
    if (threadIdx.x == 0) { g_nout = 0; g_ctr = 0; __threadfence(); }
}

extern "C" void kernel_launch(void* const* d_in, const int* in_sizes, int n_in,
                              void* d_out, int out_size) {
    const float* src = (const float*)d_in[0];   // src_V [16384,3]
    const float* tar = (const float*)d_in[1];   // tar_V [16384,3]
    float* out = (float*)d_out;

    build_kernel<<<NSRC / NTHREADS, NTHREADS>>>(src);
    search_kernel<<<SB, NTHREADS>>>(tar, out);
}

// round 15
// speedup vs baseline: 1.8454x; 1.8454x over previous
#include <cuda_runtime.h>
#include <math_constants.h>

// Problem geometry
#define NSRC 16384
#define NTAR 16384

// 2D grid over (x,y)
#define GB   5.0f                 // half-extent; N(0,1) data max |coord| ~4.3
#define GC   64                   // cells per dim
#define HH   0.15625f             // 2*GB/GC
#define INVH 6.4f                 // 1/HH
#define NCELL (GC * GC)           // 4096
#define CAP  128                  // per-cell capacity (center cells ~64; overflow -> fallback)
#define OCAP 1024                 // fallback list capacity

#define SB   2048                 // search blocks (8 targets each, warp-per-target)
#define NTHREADS 256

// Scratch (allocation-free rule: __device__ globals; zero-initialized at load,
// every counter reset by the last search block for graph replay).
__device__ int    g_cnt[NCELL];
__device__ float4 g_cell[NCELL * CAP];      // (x,y,z, -0.5*||s||^2)
__device__ float4 g_out_list[OCAP];
__device__ int    g_nout = 0;
__device__ float  g_partial[SB];
__device__ int    g_ctr = 0;

// ---------------------------------------------------------------------------
// Build: scatter sources into per-cell lists. Order within a cell is
// nondeterministic, but consumers take an order-invariant exact max.
// ---------------------------------------------------------------------------
__global__ __launch_bounds__(NTHREADS) void build_kernel(const float* __restrict__ src) {
    int i = blockIdx.x * NTHREADS + threadIdx.x;
    if (i >= NSRC) return;
    float x = src[3 * i + 0];
    float y = src[3 * i + 1];
    float z = src[3 * i + 2];
    float w = -0.5f * (x * x + y * y + z * z);
    int ix = (int)floorf((x + GB) * INVH);
    int iy = (int)floorf((y + GB) * INVH);
    if (ix >= 0 && ix < GC && iy >= 0 && iy < GC) {
        int c = iy * GC + ix;
        int p = atomicAdd(&g_cnt[c], 1);
        if (p < CAP) {
            g_cell[c * CAP + p] = make_float4(x, y, z, w);
            return;
        }
    }
    // out-of-range or cell overflow: exact fallback list (scanned by everyone)
    int o = atomicAdd(&g_nout, 1);
    if (o < OCAP) g_out_list[o] = make_float4(x, y, z, w);
}

// ---------------------------------------------------------------------------
// Search helpers
// ---------------------------------------------------------------------------
__device__ __forceinline__ float warp_max(float v) {
#pragma unroll
    for (int o = 16; o > 0; o >>= 1)
        v = fmaxf(v, __shfl_xor_sync(0xFFFFFFFFu, v, o));
    return v;
}

// Dense scan of one ROW of up to 3 adjacent cells (cx-1..cx+1) with
// pre-fetched counts; candidates walked as one flattened index space.
__device__ __forceinline__ void scan_row3(int y, int cx, int n0, int n1, int n2,
                                          float tx, float ty, float tz,
                                          int lane, float& vmax) {
    int p1 = n0, p2 = n0 + n1, N = p2 + n2;
    const float4* base = g_cell + (long long)(y * GC + cx - 1) * CAP;
    for (int i = lane; i < N; i += 32) {
        int ge1 = (i >= p1) ? 1 : 0;
        int ge2 = (i >= p2) ? 1 : 0;
        int cell = ge1 + ge2;
        int sub  = i - (ge2 ? p2 : (ge1 ? p1 : 0));
        float4 p = __ldg(base + cell * CAP + sub);
        float v = fmaf(p.x, tx, fmaf(p.y, ty, fmaf(p.z, tz, p.w)));
        vmax = fmaxf(vmax, v);
    }
}

// ---------------------------------------------------------------------------
// Search: one target per WARP. Fast path = full 3x3 window (dense row scans).
// Slow path (sparse-region stragglers) = ring expansion with LANE-PARALLEL
// cells: each lane owns ring-cells lane, lane+32, ... -> all g_cnt loads of a
// ring are concurrent (one L2 round-trip per ring, not per cell). Cell lists
// in sparse regions are short, so lane divergence is bounded.
// ---------------------------------------------------------------------------
__global__ __launch_bounds__(NTHREADS) void search_kernel(const float* __restrict__ tar,
                                                          float* __restrict__ out) {
    __shared__ float wsum[NTHREADS / 32];
    __shared__ bool  amLast;
    __shared__ float red[NTHREADS];

    const int lane = threadIdx.x & 31;
    const int wid  = threadIdx.x >> 5;
    const int t    = blockIdx.x * (NTHREADS / 32) + wid;   // one target per warp

    const float tx = tar[3 * t + 0];
    const float ty = tar[3 * t + 1];
    const float tz = tar[3 * t + 2];
    const float ht2 = 0.5f * (tx * tx + ty * ty + tz * tz);

    int cx = min(GC - 1, max(0, (int)floorf((tx + GB) * INVH)));
    int cy = min(GC - 1, max(0, (int)floorf((ty + GB) * INVH)));

    float vmax = -CUDART_INF_F;

    // Fallback list (almost always empty)
    int no = min(g_nout, OCAP);
    for (int i = lane; i < no; i += 32) {
        float4 p = __ldg(&g_out_list[i]);
        float v = fmaf(p.x, tx, fmaf(p.y, ty, fmaf(p.z, tz, p.w)));
        vmax = fmaxf(vmax, v);
    }

    // ---- fast path: full 3x3 window, counts prefetched -----------------
    int cnt[3][3];
#pragma unroll
    for (int dy = 0; dy < 3; dy++) {
        int yy = cy - 1 + dy;
#pragma unroll
        for (int dx = 0; dx < 3; dx++) {
            int xx = cx - 1 + dx;
            cnt[dy][dx] = (yy >= 0 && yy < GC && xx >= 0 && xx < GC)
                          ? min(g_cnt[yy * GC + xx], CAP) : 0;
        }
    }
#pragma unroll
    for (int dy = 0; dy < 3; dy++) {
        int yy = cy - 1 + dy;
        if (yy >= 0 && yy < GC)
            scan_row3(yy, cx, cnt[dy][0], cnt[dy][1], cnt[dy][2],
                      tx, ty, tz, lane, vmax);
    }

    float vred = warp_max(vmax);

    {
        int x0 = max(0, cx - 1), x1 = min(GC - 1, cx + 1);
        int y0 = max(0, cy - 1), y1 = min(GC - 1, cy + 1);
        float mL = (x0 > 0)      ? (tx - (-GB + (float)x0 * HH))        : CUDART_INF_F;
        float mR = (x1 < GC - 1) ? ((-GB + (float)(x1 + 1) * HH) - tx)  : CUDART_INF_F;
        float mB = (y0 > 0)      ? (ty - (-GB + (float)y0 * HH))        : CUDART_INF_F;
        float mT = (y1 < GC - 1) ? ((-GB + (float)(y1 + 1) * HH) - ty)  : CUDART_INF_F;
        float margin = fminf(fminf(mL, mR), fminf(mB, mT));

        if (ht2 - vred > 0.5f * margin * margin) {
            // ---- slow path: lane-parallel ring expansion from r = 2 -----
            for (int r = 2; r < GC; r++) {
                int nring = 8 * r;     // ring cell count (unclamped enumeration)
                for (int k = lane; k < nring; k += 32) {
                    // map k -> ring cell (xx, yy)
                    int xx, yy;
                    int side = 2 * r + 1;
                    if (k < side)            { xx = cx - r + k;            yy = cy - r; }
                    else if (k < 2 * side)   { xx = cx - r + (k - side);   yy = cy + r; }
                    else {
                        int kk = k - 2 * side;           // 0 .. 4r-3
                        yy = cy - r + 1 + (kk >> 1);
                        xx = (kk & 1) ? (cx + r) : (cx - r);
                    }
                    if (xx < 0 || xx >= GC || yy < 0 || yy >= GC) continue;
                    int c = yy * GC + xx;
                    int n = min(__ldg(&g_cnt[c]), CAP);
                    const float4* pl = g_cell + c * CAP;
                    for (int i = 0; i < n; i++) {        // lane-local scan
                        float4 p = __ldg(&pl[i]);
                        float v = fmaf(p.x, tx, fmaf(p.y, ty, fmaf(p.z, tz, p.w)));
                        vmax = fmaxf(vmax, v);
                    }
                }

                vred = warp_max(vmax);
                x0 = max(0, cx - r); x1 = min(GC - 1, cx + r);
                y0 = max(0, cy - r); y1 = min(GC - 1, cy + r);
                mL = (x0 > 0)      ? (tx - (-GB + (float)x0 * HH))        : CUDART_INF_F;
                mR = (x1 < GC - 1) ? ((-GB + (float)(x1 + 1) * HH) - tx)  : CUDART_INF_F;
                mB = (y0 > 0)      ? (ty - (-GB + (float)y0 * HH))        : CUDART_INF_F;
                mT = (y1 < GC - 1) ? ((-GB + (float)(y1 + 1) * HH) - ty)  : CUDART_INF_F;
                margin = fminf(fminf(mL, mR), fminf(mB, mT));
                if (ht2 - vred <= 0.5f * margin * margin) break;  // full grid: margin=inf
            }
        }
    }

    // 0.5*min_d2 for this target
    if (lane == 0) wsum[wid] = ht2 - vred;
    __syncthreads();

    // Block reduction over 8 warp results (fixed order)
    if (threadIdx.x == 0) {
        float s = 0.0f;
#pragma unroll
        for (int i = 0; i < NTHREADS / 32; i++) s += wsum[i];
        g_partial[blockIdx.x] = s;
        __threadfence();
        int old = atomicAdd(&g_ctr, 1);
        amLast = (old == SB - 1);
    }
    __syncthreads();
    if (!amLast) return;

    __threadfence();
    // Fixed-order deterministic final sum: thread k sums partials [8k, 8k+8)
    float acc = 0.0f;
#pragma unroll
    for (int i = 0; i < SB / NTHREADS; i++)
        acc += g_partial[threadIdx.x * (SB / NTHREADS) + i];
    red[threadIdx.x] = acc;
    __syncthreads();
#pragma unroll
    for (int stride = NTHREADS / 2; stride > 0; stride >>= 1) {
        if (threadIdx.x < stride) red[threadIdx.x] += red[threadIdx.x + stride];
        __syncthreads();
    }
    if (threadIdx.x == 0) out[0] = red[0];

    // Reset state for next graph replay (all other blocks finished reading)
    for (int i = threadIdx.x; i < NCELL; i += NTHREADS) g_cnt[i] = 0;
    if (threadIdx.x == 0) { g_nout = 0; g_ctr = 0; __threadfence(); }
}

extern "C" void kernel_launch(void* const* d_in, const int* in_sizes, int n_in,
                              void* d_out, int out_size) {
    const float* src = (const float*)d_in[0];   // src_V [16384,3]
    const float* tar = (const float*)d_in[1];   // tar_V [16384,3]
    float* out = (float*)d_out;

    build_kernel<<<NSRC / NTHREADS, NTHREADS>>>(src);
    search_kernel<<<SB, NTHREADS>>>(tar, out);
}